// round 11
// baseline (speedup 1.0000x reference)
#include <cuda_runtime.h>
#include <math.h>
#include <stdint.h>

#define Bc 2
#define Nc 1024
#define Dc 384
#define Hc 8
#define HDc 48
#define DFFc 512
#define Lc 4
#define Mrows (Bc*Nc)        // 2048
#define BNN (Bc*Nc*Nc)
#define TBL 4096

// ---------------- scratch ----------------
__device__ float g_x[Bc*Nc*Dc];
__device__ float g_q[Bc*Nc*Dc];
__device__ float g_k[Bc*Nc*Dc];
__device__ float g_v[Bc*Nc*Dc];
__device__ float g_attnv[Bc*Nc*Dc];
__device__ float g_mlogits[BNN];                  // 8 MB merged logits
__device__ float g_S[Bc*Nc*Nc*3];                 // 24 MB colsum_m(orientation)
__device__ float g_bias[(size_t)Lc*BNN];          // 32 MB dis-bias (mask folded)
__device__ float g_tbl[Lc][TBL+1];
__device__ float g_v3d[Mrows*3];
__device__ float g_frame[Mrows*3];
__device__ float g_ff[Mrows*DFFc];

// ---------------- helpers ----------------
__device__ __forceinline__ uint32_t f2tf(float x) {
    uint32_t u;
    asm("cvt.rna.tf32.f32 %0, %1;" : "=r"(u) : "f"(x));
    return u;
}
__device__ __forceinline__ void mma_tf32(float d[4], const uint32_t a[4], const uint32_t b[2]) {
    asm volatile("mma.sync.aligned.m16n8k8.row.col.f32.tf32.tf32.f32 "
        "{%0,%1,%2,%3}, {%4,%5,%6,%7}, {%8,%9}, {%0,%1,%2,%3};"
        : "+f"(d[0]), "+f"(d[1]), "+f"(d[2]), "+f"(d[3])
        : "r"(a[0]), "r"(a[1]), "r"(a[2]), "r"(a[3]), "r"(b[0]), "r"(b[1]));
}

// ---------------- S[b,i,j,n] = sum_m orientation[b,i,j,m,n] ----------------
__global__ void precomp_S(const float* __restrict__ orient, float* __restrict__ S) {
    int idx = blockIdx.x * blockDim.x + threadIdx.x;
    if (idx >= BNN) return;
    const float* o = orient + (size_t)idx * 9;
    S[idx*3+0] = o[0] + o[3] + o[6];
    S[idx*3+1] = o[1] + o[4] + o[7];
    S[idx*3+2] = o[2] + o[5] + o[8];
}

// ---------------- per-layer RBF bias lookup table ----------------
__global__ void table_kernel(const float* __restrict__ Wmlp, const float* __restrict__ bmlp) {
    int i = blockIdx.x * blockDim.x + threadIdx.x;
    if (i >= Lc*(TBL+1)) return;
    int l = i / (TBL+1), t = i % (TBL+1);
    float d = 20.f * (float)t / (float)TBL;
    float acc = bmlp[l];
    const float invsig = 0.8f;
#pragma unroll
    for (int r = 0; r < 16; r++) {
        float mu = (20.f/15.f) * (float)r;
        float u = (d - mu) * invsig;
        acc += Wmlp[l*16 + r] * expf(-u*u);
    }
    g_tbl[l][t] = acc;
}

// ---------------- bias_all[l][p] = mask? -1e9 : lerp(table_l, dist[p]) ----------------
__global__ void bias_kernel(const float* __restrict__ dist, const int* __restrict__ mask,
                            float* __restrict__ bias_all) {
    int p = blockIdx.x * blockDim.x + threadIdx.x;
    if (p >= BNN) return;
    float d = dist[p];
    bool m0 = (mask[p] == 0);
    float fi = fmaxf(d, 0.f) * ((float)TBL / 20.f);
    int i0 = min((int)fi, TBL-1);
    float fr = fi - (float)i0;
#pragma unroll
    for (int l = 0; l < Lc; l++) {
        float t0 = g_tbl[l][i0], t1 = g_tbl[l][i0+1];
        float v = t0 + fr * (t1 - t0);
        bias_all[(size_t)l*BNN + p] = m0 ? -1e9f : v;
    }
}

// ---------------- TF32 MMA GEMM with optional fused LayerNorm on A ----------------
// When lng != nullptr: A2 must equal A, K == K1 (384), and the kernel normalizes
// each A row with per-row stats computed in a prologue, then applies g/b.
__device__ __forceinline__ void gemm_mma_core(
    const float* __restrict__ A, const float* __restrict__ A2, int K1, int K,
    const float* __restrict__ W, const float* __restrict__ bias,
    float* __restrict__ C, const float* __restrict__ Cres, int Nout, int relu,
    const float* __restrict__ lng, const float* __restrict__ lnb,
    uint32_t (*As)[36], uint32_t (*Bs)[72], float* mrow, float* irow)
{
    int bm = blockIdx.y * 64, bn = blockIdx.x * 64;
    int tid = threadIdx.x;
    int warp = tid >> 5, lane = tid & 31;
    int wm = (warp & 1) * 32, wn = (warp >> 1) * 32;
    int g = lane >> 2, t = lane & 3;
    int K2 = K - K1;
    if (lng) {
        // per-row LN stats: thread pair (tid>>1, halves) scans 192 floats each
        int row = tid >> 1, half = tid & 1;
        const float* ar = A + (size_t)(bm + row)*K1 + half*192;
        float s = 0.f, s2 = 0.f;
#pragma unroll
        for (int i = 0; i < 48; i++) {
            float4 a = *(const float4*)&ar[i*4];
            s  += a.x + a.y + a.z + a.w;
            s2 += a.x*a.x + a.y*a.y + a.z*a.z + a.w*a.w;
        }
        s  += __shfl_xor_sync(0xffffffffu, s, 1);
        s2 += __shfl_xor_sync(0xffffffffu, s2, 1);
        float mean = s * (1.f/384.f);
        float var  = s2 * (1.f/384.f) - mean*mean;
        mrow[row] = mean;
        irow[row] = rsqrtf(var + 1e-5f);
        __syncthreads();
    }
    float acc[2][4][4] = {};
    int ktiles = (K + 31) >> 5;
    for (int kt = 0; kt < ktiles; kt++) {
        int k0 = kt << 5;
        if (k0 + 32 <= K1) {
#pragma unroll
            for (int it = 0; it < 4; it++) {
                int idx = tid*4 + it*512;
                int m = idx >> 5, c = idx & 31;
                float4 a = *(const float4*)&A[(size_t)(bm+m)*K1 + k0 + c];
                if (lng) {
                    float m_ = mrow[m], iv = irow[m];
                    float4 gv = *(const float4*)&lng[k0+c];
                    float4 bv = *(const float4*)&lnb[k0+c];
                    a.x = (a.x - m_)*iv*gv.x + bv.x;
                    a.y = (a.y - m_)*iv*gv.y + bv.y;
                    a.z = (a.z - m_)*iv*gv.z + bv.z;
                    a.w = (a.w - m_)*iv*gv.w + bv.w;
                }
                uint4 u = {f2tf(a.x), f2tf(a.y), f2tf(a.z), f2tf(a.w)};
                *(uint4*)&As[m][c] = u;
            }
        } else {
#pragma unroll
            for (int it = 0; it < 4; it++) {
                int idx = tid*4 + it*512;
                int m = idx >> 5, c = idx & 31;
#pragma unroll
                for (int jj = 0; jj < 4; jj++) {
                    int kg = k0 + c + jj;
                    float val = 0.f;
                    if (kg < K) val = (kg < K1) ? A[(size_t)(bm+m)*K1 + kg]
                                                : A2[(size_t)(bm+m)*K2 + kg - K1];
                    As[m][c+jj] = f2tf(val);
                }
            }
        }
#pragma unroll
        for (int it = 0; it < 4; it++) {
            int idx = tid*4 + it*512;
            int kk = idx >> 6, c = idx & 63;
            int kg = k0 + kk;
            float4 wv = make_float4(0.f, 0.f, 0.f, 0.f);
            if (kg < K) wv = *(const float4*)&W[(size_t)kg*Nout + bn + c];
            uint4 u = {f2tf(wv.x), f2tf(wv.y), f2tf(wv.z), f2tf(wv.w)};
            *(uint4*)&Bs[kk][c] = u;
        }
        __syncthreads();
#pragma unroll
        for (int k8 = 0; k8 < 4; k8++) {
            int kb = k8 * 8;
            uint32_t a[2][4], bf[4][2];
#pragma unroll
            for (int i = 0; i < 2; i++) {
                int r0 = wm + 16*i + g;
                a[i][0] = As[r0  ][kb + t];
                a[i][1] = As[r0+8][kb + t];
                a[i][2] = As[r0  ][kb + t + 4];
                a[i][3] = As[r0+8][kb + t + 4];
            }
#pragma unroll
            for (int j = 0; j < 4; j++) {
                int cn = wn + 8*j + g;
                bf[j][0] = Bs[kb + t    ][cn];
                bf[j][1] = Bs[kb + t + 4][cn];
            }
#pragma unroll
            for (int i = 0; i < 2; i++)
#pragma unroll
                for (int j = 0; j < 4; j++)
                    mma_tf32(acc[i][j], a[i], bf[j]);
        }
        __syncthreads();
    }
#pragma unroll
    for (int i = 0; i < 2; i++) {
#pragma unroll
        for (int j = 0; j < 4; j++) {
            int ng = bn + wn + 8*j + 2*t;
            float b0 = bias[ng], b1 = bias[ng+1];
#pragma unroll
            for (int rr = 0; rr < 2; rr++) {
                int mg = bm + wm + 16*i + g + 8*rr;
                float o0 = acc[i][j][rr*2+0] + b0;
                float o1 = acc[i][j][rr*2+1] + b1;
                if (relu) { o0 = fmaxf(o0, 0.f); o1 = fmaxf(o1, 0.f); }
                if (Cres) {
                    float2 rv = *(const float2*)&Cres[(size_t)mg*Nout + ng];
                    o0 += rv.x; o1 += rv.y;
                }
                float2 o = {o0, o1};
                *(float2*)&C[(size_t)mg*Nout + ng] = o;
            }
        }
    }
}

__global__ __launch_bounds__(128) void gemm_mma_kernel(
    const float* __restrict__ A, const float* __restrict__ A2, int K1, int K,
    const float* __restrict__ W, const float* __restrict__ bias,
    float* __restrict__ C, const float* __restrict__ Cres, int Nout, int relu,
    const float* __restrict__ lng, const float* __restrict__ lnb) {
    __shared__ uint32_t As[64][36];
    __shared__ uint32_t Bs[32][72];
    __shared__ float mrow[64], irow[64];
    gemm_mma_core(A, A2, K1, K, W, bias, C, Cres, Nout, relu, lng, lnb, As, Bs, mrow, irow);
}

__global__ __launch_bounds__(128) void gemm3_mma_kernel(const float* __restrict__ A,
                             const float* __restrict__ W0, const float* __restrict__ W1, const float* __restrict__ W2,
                             const float* __restrict__ b0, const float* __restrict__ b1, const float* __restrict__ b2,
                             float* __restrict__ C0, float* __restrict__ C1, float* __restrict__ C2,
                             const float* __restrict__ lng, const float* __restrict__ lnb) {
    __shared__ uint32_t As[64][36];
    __shared__ uint32_t Bs[32][72];
    __shared__ float mrow[64], irow[64];
    int z = blockIdx.z;
    const float* W = (z == 0) ? W0 : (z == 1) ? W1 : W2;
    const float* b = (z == 0) ? b0 : (z == 1) ? b1 : b2;
    float* C = (z == 0) ? C0 : (z == 1) ? C1 : C2;
    gemm_mma_core(A, A, Dc, Dc, W, b, C, nullptr, Dc, 0, lng, lnb, As, Bs, mrow, irow);
}

// ---------------- v3d with fused LN: warp-per-row LN(x[row]) @ W3 + b3 ----------------
__global__ void v3_kernel(const float* __restrict__ x,
                          const float* __restrict__ lng, const float* __restrict__ lnb,
                          const float* __restrict__ W3, const float* __restrict__ b3,
                          float* __restrict__ out) {
    int warp = (blockIdx.x * blockDim.x + threadIdx.x) >> 5;
    int lane = threadIdx.x & 31;
    if (warp >= Mrows) return;
    const float* xr = x + (size_t)warp*Dc;
    float xv[12];
    float s = 0.f, sq = 0.f;
#pragma unroll
    for (int i = 0; i < 12; i++) {
        float v = xr[lane + i*32];
        xv[i] = v; s += v; sq += v*v;
    }
#pragma unroll
    for (int off = 16; off > 0; off >>= 1) {
        s  += __shfl_xor_sync(0xffffffffu, s, off);
        sq += __shfl_xor_sync(0xffffffffu, sq, off);
    }
    float mean = s * (1.f/384.f);
    float inv = rsqrtf(sq * (1.f/384.f) - mean*mean + 1e-5f);
    float s0 = 0.f, s1 = 0.f, s2 = 0.f;
#pragma unroll
    for (int i = 0; i < 12; i++) {
        int c = lane + i*32;
        float hv = (xv[i] - mean)*inv*lng[c] + lnb[c];
        s0 += hv * W3[c*3+0];
        s1 += hv * W3[c*3+1];
        s2 += hv * W3[c*3+2];
    }
#pragma unroll
    for (int off = 16; off > 0; off >>= 1) {
        s0 += __shfl_down_sync(0xffffffffu, s0, off);
        s1 += __shfl_down_sync(0xffffffffu, s1, off);
        s2 += __shfl_down_sync(0xffffffffu, s2, off);
    }
    if (lane == 0) {
        out[warp*3+0] = s0 + b3[0];
        out[warp*3+1] = s1 + b3[1];
        out[warp*3+2] = s2 + b3[2];
    }
}

// ---------------- combined attention: flash (blocks 0..255) + qkfull (256..767) ----------------
__device__ void flash_part(uint32_t* smem,
    const float* __restrict__ q, const float* __restrict__ k, const float* __restrict__ v,
    const float* __restrict__ bias, float* __restrict__ attn_out, int bid)
{
    uint32_t* qs = smem;             // [q][d] stride 52
    uint32_t* UB = smem + 64*52;     // ks stride 52 / vs stride 56
    uint32_t* ps = smem + 64*52 + 64*56;  // [q][k'] stride 68
    int b = bid >> 7, h = (bid >> 4) & 7, q0 = (bid & 15) * 64;
    int tid = threadIdx.x;
    int warp = tid >> 5, lane = tid & 31;
    int g = lane >> 2, t = lane & 3;
    int wq = warp * 16;

    for (int i = tid; i < 768; i += 128) {
        int r = i / 12, c = (i % 12) * 4;
        float4 vv = *(const float4*)&q[(size_t)(b*Nc + q0 + r)*Dc + h*HDc + c];
        qs[r*52+c] = f2tf(vv.x); qs[r*52+c+1] = f2tf(vv.y);
        qs[r*52+c+2] = f2tf(vv.z); qs[r*52+c+3] = f2tf(vv.w);
    }
    float O[6][4] = {};
    float rsum0 = 0.f, rsum1 = 0.f;
    const float scale = 0.14433756729740643f;

    for (int kt = 0; kt < 16; kt++) {
        int k0 = kt * 64;
        for (int i = tid; i < 768; i += 128) {
            int r = i / 12, c = (i % 12) * 4;
            float4 vv = *(const float4*)&k[(size_t)(b*Nc + k0 + r)*Dc + h*HDc + c];
            UB[r*52+c] = f2tf(vv.x); UB[r*52+c+1] = f2tf(vv.y);
            UB[r*52+c+2] = f2tf(vv.z); UB[r*52+c+3] = f2tf(vv.w);
        }
        __syncthreads();
        float sacc[8][4] = {};
#pragma unroll
        for (int d8 = 0; d8 < 6; d8++) {
            uint32_t a[4];
            a[0] = qs[(wq + g)*52 + d8*8 + t];
            a[1] = qs[(wq + g + 8)*52 + d8*8 + t];
            a[2] = qs[(wq + g)*52 + d8*8 + t + 4];
            a[3] = qs[(wq + g + 8)*52 + d8*8 + t + 4];
#pragma unroll
            for (int j = 0; j < 8; j++) {
                uint32_t bb[2];
                bb[0] = UB[(8*j + g)*52 + d8*8 + t];
                bb[1] = UB[(8*j + g)*52 + d8*8 + t + 4];
                mma_tf32(sacc[j], a, bb);
            }
        }
#pragma unroll
        for (int j = 0; j < 8; j++) {
            int c = 8*j + 2*t;
            size_t row0 = (size_t)(b*Nc + q0 + wq + g);
            float2 d0 = *(const float2*)&bias[row0*Nc + k0 + c];
            float2 d1 = *(const float2*)&bias[(row0 + 8)*Nc + k0 + c];
            float e00 = __expf(sacc[j][0]*scale + d0.x);
            float e01 = __expf(sacc[j][1]*scale + d0.y);
            float e10 = __expf(sacc[j][2]*scale + d1.x);
            float e11 = __expf(sacc[j][3]*scale + d1.y);
            rsum0 += e00 + e01; rsum1 += e10 + e11;
            ps[(wq + g)*68 + c]     = f2tf(e00);
            ps[(wq + g)*68 + c + 1] = f2tf(e01);
            ps[(wq + g + 8)*68 + c]     = f2tf(e10);
            ps[(wq + g + 8)*68 + c + 1] = f2tf(e11);
        }
        __syncthreads();
        for (int i = tid; i < 768; i += 128) {
            int r = i / 12, c = (i % 12) * 4;
            float4 vv = *(const float4*)&v[(size_t)(b*Nc + k0 + r)*Dc + h*HDc + c];
            UB[r*56+c] = f2tf(vv.x); UB[r*56+c+1] = f2tf(vv.y);
            UB[r*56+c+2] = f2tf(vv.z); UB[r*56+c+3] = f2tf(vv.w);
        }
        __syncthreads();
#pragma unroll
        for (int j8 = 0; j8 < 8; j8++) {
            uint32_t a[4];
            a[0] = ps[(wq + g)*68 + 8*j8 + t];
            a[1] = ps[(wq + g + 8)*68 + 8*j8 + t];
            a[2] = ps[(wq + g)*68 + 8*j8 + t + 4];
            a[3] = ps[(wq + g + 8)*68 + 8*j8 + t + 4];
#pragma unroll
            for (int dn = 0; dn < 6; dn++) {
                uint32_t bb[2];
                bb[0] = UB[(8*j8 + t)*56 + 8*dn + g];
                bb[1] = UB[(8*j8 + t + 4)*56 + 8*dn + g];
                mma_tf32(O[dn], a, bb);
            }
        }
        __syncthreads();
    }
#pragma unroll
    for (int off = 1; off <= 2; off <<= 1) {
        rsum0 += __shfl_xor_sync(0xffffffffu, rsum0, off);
        rsum1 += __shfl_xor_sync(0xffffffffu, rsum1, off);
    }
    float rinv0 = 1.f / rsum0, rinv1 = 1.f / rsum1;
#pragma unroll
    for (int dn = 0; dn < 6; dn++) {
        int c = 8*dn + 2*t;
        float2 o0 = {O[dn][0]*rinv0, O[dn][1]*rinv0};
        float2 o1 = {O[dn][2]*rinv1, O[dn][3]*rinv1};
        *(float2*)&attn_out[(size_t)(b*Nc + q0 + wq + g)*Dc + h*HDc + c]     = o0;
        *(float2*)&attn_out[(size_t)(b*Nc + q0 + wq + g + 8)*Dc + h*HDc + c] = o1;
    }
}

__device__ void qkfull_part(uint32_t* smem,
    const float* __restrict__ q, const float* __restrict__ k,
    const float* __restrict__ bias, float* __restrict__ mlog, int qid)
{
    uint32_t* qs = smem;           // [q][64] stride 68
    uint32_t* ks = smem + 64*68;
    int b = qid >> 8, q0 = ((qid >> 4) & 15) * 64, k0 = (qid & 15) * 64;
    int tid = threadIdx.x;
    int warp = tid >> 5, lane = tid & 31;
    int g = lane >> 2, t = lane & 3;
    int wq = warp * 16;
    float sacc[8][4] = {};
    for (int dt = 0; dt < 6; dt++) {
        int d0 = dt * 64;
        for (int i = tid; i < 1024; i += 128) {
            int r = i >> 4, c = (i & 15) * 4;
            float4 vq = *(const float4*)&q[(size_t)(b*Nc + q0 + r)*Dc + d0 + c];
            qs[r*68+c] = f2tf(vq.x); qs[r*68+c+1] = f2tf(vq.y);
            qs[r*68+c+2] = f2tf(vq.z); qs[r*68+c+3] = f2tf(vq.w);
            float4 vk = *(const float4*)&k[(size_t)(b*Nc + k0 + r)*Dc + d0 + c];
            ks[r*68+c] = f2tf(vk.x); ks[r*68+c+1] = f2tf(vk.y);
            ks[r*68+c+2] = f2tf(vk.z); ks[r*68+c+3] = f2tf(vk.w);
        }
        __syncthreads();
#pragma unroll
        for (int d8 = 0; d8 < 8; d8++) {
            uint32_t a[4];
            a[0] = qs[(wq + g)*68 + d8*8 + t];
            a[1] = qs[(wq + g + 8)*68 + d8*8 + t];
            a[2] = qs[(wq + g)*68 + d8*8 + t + 4];
            a[3] = qs[(wq + g + 8)*68 + d8*8 + t + 4];
#pragma unroll
            for (int j = 0; j < 8; j++) {
                uint32_t bb[2];
                bb[0] = ks[(8*j + g)*68 + d8*8 + t];
                bb[1] = ks[(8*j + g)*68 + d8*8 + t + 4];
                mma_tf32(sacc[j], a, bb);
            }
        }
        __syncthreads();
    }
    const float scale = 0.14433756729740643f;
#pragma unroll
    for (int j = 0; j < 8; j++) {
        int c = 8*j + 2*t;
        size_t row0 = (size_t)(b*Nc + q0 + wq + g);
        float2 d0 = *(const float2*)&bias[row0*Nc + k0 + c];
        float2 d1 = *(const float2*)&bias[(row0 + 8)*Nc + k0 + c];
        float2 w0 = {sacc[j][0]*scale + 8.f*d0.x, sacc[j][1]*scale + 8.f*d0.y};
        float2 w1 = {sacc[j][2]*scale + 8.f*d1.x, sacc[j][3]*scale + 8.f*d1.y};
        *(float2*)&mlog[row0*Nc + k0 + c]       = w0;
        *(float2*)&mlog[(row0 + 8)*Nc + k0 + c] = w1;
    }
}

__global__ __launch_bounds__(128) void attn_kernel(
    const float* __restrict__ q, const float* __restrict__ k, const float* __restrict__ v,
    const float* __restrict__ bias, float* __restrict__ attn_out, float* __restrict__ mlog)
{
    __shared__ uint32_t smem[64*52 + 64*56 + 64*68];   // 45056 B (flash union; qkfull uses 34816 B)
    int bx = blockIdx.x;
    if (bx < 256) flash_part(smem, q, k, v, bias, attn_out, bx);
    else          qkfull_part(smem, q, k, bias, mlog, bx - 256);
}

// ---------------- merged softmax + geometric frame (fused, reads mlogits) ----------------
__global__ void merged_frame_kernel(const float* __restrict__ mlog,
                                    const float* __restrict__ ad, const float* __restrict__ S,
                                    const float* __restrict__ v3d, float* __restrict__ frame) {
    int row = blockIdx.x;          // b*N + i
    int b = row >> 10;
    int tid = threadIdx.x;         // 256
    __shared__ float probs[Nc];
    __shared__ float v3s[Nc*3];
    __shared__ float sh[256];
    for (int tn = tid; tn < 768; tn += 256)
        *(float4*)&v3s[tn*4] = *(const float4*)&v3d[b*Nc*3 + tn*4];
    float4 lv = *(const float4*)&mlog[(size_t)row*Nc + tid*4];
    float e0 = __expf(lv.x), e1 = __expf(lv.y), e2 = __expf(lv.z), e3 = __expf(lv.w);
    sh[tid] = e0 + e1 + e2 + e3; __syncthreads();
    for (int st = 128; st > 0; st >>= 1) {
        if (tid < st) sh[tid] += sh[tid+st];
        __syncthreads();
    }
    float inv = 1.f / sh[0];
    float4 pr = {e0*inv, e1*inv, e2*inv, e3*inv};
    *(float4*)&probs[tid*4] = pr;
    __syncthreads();
    float cx = 0.f, cy = 0.f, cz = 0.f;
    {
        int j0 = tid * 4;
        size_t base = ((size_t)row*Nc + j0)*3;
        float4 A0 = *(const float4*)&ad[base];
        float4 A1 = *(const float4*)&ad[base+4];
        float4 A2 = *(const float4*)&ad[base+8];
        float4 S0 = *(const float4*)&S[base];
        float4 S1 = *(const float4*)&S[base+4];
        float4 S2 = *(const float4*)&S[base+8];
        float af[12] = {A0.x,A0.y,A0.z,A0.w,A1.x,A1.y,A1.z,A1.w,A2.x,A2.y,A2.z,A2.w};
        float sf[12] = {S0.x,S0.y,S0.z,S0.w,S1.x,S1.y,S1.z,S1.w,S2.x,S2.y,S2.z,S2.w};
#pragma unroll
        for (int jj = 0; jj < 4; jj++) {
            int j = j0 + jj;
            float m = probs[j];
            float ax = af[jj*3+0], ay = af[jj*3+1], az = af[jj*3+2];
            float bx = sf[jj*3+0]*v3s[j*3+0];
            float by = sf[jj*3+1]*v3s[j*3+1];
            float bz = sf[jj*3+2]*v3s[j*3+2];
            cx += m * (ay*bz - az*by);
            cy += m * (az*bx - ax*bz);
            cz += m * (ax*by - ay*bx);
        }
    }
    float vals[3] = {cx, cy, cz};
#pragma unroll
    for (int c = 0; c < 3; c++) {
        sh[tid] = vals[c]; __syncthreads();
        for (int st = 128; st > 0; st >>= 1) {
            if (tid < st) sh[tid] += sh[tid+st];
            __syncthreads();
        }
        if (tid == 0) frame[row*3 + c] = sh[0] * (1.f/Nc);
        __syncthreads();
    }
}

// ---------------- host driver ----------------
extern "C" void kernel_launch(void* const* d_in, const int* in_sizes, int n_in,
                              void* d_out, int out_size) {
    const float* x_rigid = (const float*)d_in[0];
    const float* ad      = (const float*)d_in[1];
    const float* orient  = (const float*)d_in[2];
    const float* dist    = (const float*)d_in[3];
    const int*   amask   = (const int*)  d_in[4];
    const float* Wq   = (const float*)d_in[5];
    const float* bq   = (const float*)d_in[6];
    const float* Wk   = (const float*)d_in[7];
    const float* bk   = (const float*)d_in[8];
    const float* Wv   = (const float*)d_in[9];
    const float* bv   = (const float*)d_in[10];
    const float* W3   = (const float*)d_in[11];
    const float* b3   = (const float*)d_in[12];
    const float* Wmlp = (const float*)d_in[13];
    const float* bmlp = (const float*)d_in[14];
    const float* Wfc  = (const float*)d_in[15];
    const float* bfc  = (const float*)d_in[16];
    const float* Wff1 = (const float*)d_in[17];
    const float* bff1 = (const float*)d_in[18];
    const float* Wff2 = (const float*)d_in[19];
    const float* bff2 = (const float*)d_in[20];
    const float* ln1g = (const float*)d_in[21];
    const float* ln1b = (const float*)d_in[22];
    const float* ln2g = (const float*)d_in[23];
    const float* ln2b = (const float*)d_in[24];

    float *px, *pq, *pk, *pv, *pav, *pml, *pS, *pbias, *pv3, *pfr, *pff;
    cudaGetSymbolAddress((void**)&px,  g_x);
    cudaGetSymbolAddress((void**)&pq,  g_q);
    cudaGetSymbolAddress((void**)&pk,  g_k);
    cudaGetSymbolAddress((void**)&pv,  g_v);
    cudaGetSymbolAddress((void**)&pav, g_attnv);
    cudaGetSymbolAddress((void**)&pml, g_mlogits);
    cudaGetSymbolAddress((void**)&pS,  g_S);
    cudaGetSymbolAddress((void**)&pbias, g_bias);
    cudaGetSymbolAddress((void**)&pv3, g_v3d);
    cudaGetSymbolAddress((void**)&pfr, g_frame);
    cudaGetSymbolAddress((void**)&pff, g_ff);

    precomp_S<<<(BNN+255)/256, 256>>>(orient, pS);
    table_kernel<<<(Lc*(TBL+1)+255)/256, 256>>>(Wmlp, bmlp);
    bias_kernel<<<(BNN+255)/256, 256>>>(dist, amask, pbias);

    dim3 gQKV3(Dc/64, Mrows/64, 3);   // (6,32,3)
    dim3 gFC(Dc/64, Mrows/64);        // (6,32)
    dim3 gFF1(DFFc/64, Mrows/64);     // (8,32)

    for (int l = 0; l < Lc; l++) {
        const float* xin = (l == 0) ? x_rigid : px;
        float* ff2out = (l == Lc-1) ? (float*)d_out : px;
        gemm3_mma_kernel<<<gQKV3, 128>>>(xin, Wq + l*Dc*Dc, Wk + l*Dc*Dc, Wv + l*Dc*Dc,
                                         bq + l*Dc, bk + l*Dc, bv + l*Dc, pq, pk, pv,
                                         ln1g + l*Dc, ln1b + l*Dc);
        v3_kernel<<<Mrows/8, 256>>>(xin, ln1g + l*Dc, ln1b + l*Dc, W3 + l*Dc*3, b3 + l*3, pv3);
        attn_kernel<<<768, 128>>>(pq, pk, pv, pbias + (size_t)l*BNN, pav, pml);
        merged_frame_kernel<<<Mrows, 256>>>(pml, ad, pS, pv3, pfr);
        gemm_mma_kernel<<<gFC, 128>>>(pav, pfr, Dc, Dc+3, Wfc + l*(Dc+3)*Dc, bfc + l*Dc,
                                      px, xin, Dc, 0, nullptr, nullptr);
        gemm_mma_kernel<<<gFF1, 128>>>(px, px, Dc, Dc, Wff1 + l*Dc*DFFc, bff1 + l*DFFc,
                                       pff, nullptr, DFFc, 1, ln2g + l*Dc, ln2b + l*Dc);
        gemm_mma_kernel<<<gFC, 128>>>(pff, pff, DFFc, DFFc, Wff2 + l*DFFc*Dc, bff2 + l*Dc,
                                      ff2out, px, Dc, 0, nullptr, nullptr);
    }
}

// round 12
// speedup vs baseline: 1.3437x; 1.3437x over previous
#include <cuda_runtime.h>
#include <math.h>
#include <stdint.h>

#define Bc 2
#define Nc 1024
#define Dc 384
#define Hc 8
#define HDc 48
#define DFFc 512
#define Lc 4
#define Mrows (Bc*Nc)        // 2048
#define BNN (Bc*Nc*Nc)
#define TBL 4096

// ---------------- scratch ----------------
__device__ float g_x[Bc*Nc*Dc];
__device__ float g_q[Bc*Nc*Dc];
__device__ float g_k[Bc*Nc*Dc];
__device__ float g_v[Bc*Nc*Dc];
__device__ float g_attnv[Bc*Nc*Dc];
__device__ float g_mlogits[BNN];                  // 8 MB merged logits
__device__ float g_S[Bc*Nc*Nc*3];                 // 24 MB colsum_m(orientation)
__device__ float g_bias[(size_t)Lc*BNN];          // 32 MB dis-bias (mask folded)
__device__ float g_tbl[Lc][TBL+1];
__device__ float g_v3d[Mrows*3];
__device__ float g_frame[Mrows*3];
__device__ float g_ff[Mrows*DFFc];

// ---------------- helpers ----------------
__device__ __forceinline__ uint32_t f2tf(float x) {
    uint32_t u;
    asm("cvt.rna.tf32.f32 %0, %1;" : "=r"(u) : "f"(x));
    return u;
}
__device__ __forceinline__ void mma_tf32(float d[4], const uint32_t a[4], const uint32_t b[2]) {
    asm volatile("mma.sync.aligned.m16n8k8.row.col.f32.tf32.tf32.f32 "
        "{%0,%1,%2,%3}, {%4,%5,%6,%7}, {%8,%9}, {%0,%1,%2,%3};"
        : "+f"(d[0]), "+f"(d[1]), "+f"(d[2]), "+f"(d[3])
        : "r"(a[0]), "r"(a[1]), "r"(a[2]), "r"(a[3]), "r"(b[0]), "r"(b[1]));
}

// ---------------- S[b,i,j,n] = sum_m orientation[b,i,j,m,n] ----------------
__global__ void precomp_S(const float* __restrict__ orient, float* __restrict__ S) {
    int idx = blockIdx.x * blockDim.x + threadIdx.x;
    if (idx >= BNN) return;
    const float* o = orient + (size_t)idx * 9;
    S[idx*3+0] = o[0] + o[3] + o[6];
    S[idx*3+1] = o[1] + o[4] + o[7];
    S[idx*3+2] = o[2] + o[5] + o[8];
}

// ---------------- per-layer RBF bias lookup table ----------------
__global__ void table_kernel(const float* __restrict__ Wmlp, const float* __restrict__ bmlp) {
    int i = blockIdx.x * blockDim.x + threadIdx.x;
    if (i >= Lc*(TBL+1)) return;
    int l = i / (TBL+1), t = i % (TBL+1);
    float d = 20.f * (float)t / (float)TBL;
    float acc = bmlp[l];
    const float invsig = 0.8f;
#pragma unroll
    for (int r = 0; r < 16; r++) {
        float mu = (20.f/15.f) * (float)r;
        float u = (d - mu) * invsig;
        acc += Wmlp[l*16 + r] * expf(-u*u);
    }
    g_tbl[l][t] = acc;
}

// ---------------- bias_all[l][p] = mask? -1e9 : lerp(table_l, dist[p]) ----------------
__global__ void bias_kernel(const float* __restrict__ dist, const int* __restrict__ mask,
                            float* __restrict__ bias_all) {
    int p = blockIdx.x * blockDim.x + threadIdx.x;
    if (p >= BNN) return;
    float d = dist[p];
    bool m0 = (mask[p] == 0);
    float fi = fmaxf(d, 0.f) * ((float)TBL / 20.f);
    int i0 = min((int)fi, TBL-1);
    float fr = fi - (float)i0;
#pragma unroll
    for (int l = 0; l < Lc; l++) {
        float t0 = g_tbl[l][i0], t1 = g_tbl[l][i0+1];
        float v = t0 + fr * (t1 - t0);
        bias_all[(size_t)l*BNN + p] = m0 ? -1e9f : v;
    }
}

// ---------------- TF32 MMA GEMM: 64x64 tile, BK=32, double-buffered pipeline ----------------
// Optional fused LayerNorm on A (lng != nullptr requires K == K1 == 384).
__device__ __forceinline__ void gemm_mma_core(
    const float* __restrict__ A, const float* __restrict__ A2, int K1, int K,
    const float* __restrict__ W, const float* __restrict__ bias,
    float* __restrict__ C, const float* __restrict__ Cres, int Nout, int relu,
    const float* __restrict__ lng, const float* __restrict__ lnb,
    uint32_t* sm, float* mrow, float* irow)
{
    int bm = blockIdx.y * 64, bn = blockIdx.x * 64;
    int tid = threadIdx.x;
    int warp = tid >> 5, lane = tid & 31;
    int wm = (warp & 1) * 32, wn = (warp >> 1) * 32;
    int g = lane >> 2, t = lane & 3;
    int K2 = K - K1;
    int mbase = tid >> 3, ca = (tid & 7) * 4;     // A: row mbase+16*it, cols ca..ca+3
    int kbase = tid >> 4, cb = (tid & 15) * 4;    // B: row kbase+8*it, cols cb..cb+3

    if (lng) {
        int row = tid >> 1, half = tid & 1;
        const float* ar = A + (size_t)(bm + row)*K1 + half*192;
        float s = 0.f, s2 = 0.f;
#pragma unroll
        for (int i = 0; i < 48; i++) {
            float4 a = *(const float4*)&ar[i*4];
            s  += a.x + a.y + a.z + a.w;
            s2 += a.x*a.x + a.y*a.y + a.z*a.z + a.w*a.w;
        }
        s  += __shfl_xor_sync(0xffffffffu, s, 1);
        s2 += __shfl_xor_sync(0xffffffffu, s2, 1);
        float mean = s * (1.f/384.f);
        mrow[row] = mean;
        irow[row] = rsqrtf(s2 * (1.f/384.f) - mean*mean + 1e-5f);
        __syncthreads();
    }

    float4 ra[4], rb[4];
    auto load_tile = [&](int k0) {
        if (k0 + 32 <= K1) {
#pragma unroll
            for (int it = 0; it < 4; it++) {
                int m = mbase + it*16;
                float4 a = *(const float4*)&A[(size_t)(bm+m)*K1 + k0 + ca];
                if (lng) {
                    float mm = mrow[m], iv = irow[m];
                    float4 gv = *(const float4*)&lng[k0+ca];
                    float4 bv = *(const float4*)&lnb[k0+ca];
                    a.x = (a.x-mm)*iv*gv.x + bv.x;
                    a.y = (a.y-mm)*iv*gv.y + bv.y;
                    a.z = (a.z-mm)*iv*gv.z + bv.z;
                    a.w = (a.w-mm)*iv*gv.w + bv.w;
                }
                ra[it] = a;
            }
        } else {
#pragma unroll
            for (int it = 0; it < 4; it++) {
                int m = mbase + it*16;
                float vv[4];
#pragma unroll
                for (int jj = 0; jj < 4; jj++) {
                    int kg = k0 + ca + jj;
                    float val = 0.f;
                    if (kg < K) val = (kg < K1) ? A[(size_t)(bm+m)*K1 + kg]
                                                : A2[(size_t)(bm+m)*K2 + kg - K1];
                    vv[jj] = val;
                }
                ra[it] = make_float4(vv[0], vv[1], vv[2], vv[3]);
            }
        }
#pragma unroll
        for (int it = 0; it < 4; it++) {
            int kg = k0 + kbase + it*8;
            float4 wv = make_float4(0.f, 0.f, 0.f, 0.f);
            if (kg < K) wv = *(const float4*)&W[(size_t)kg*Nout + bn + cb];
            rb[it] = wv;
        }
    };
    auto sts_tile = [&](int bsel) {
        uint32_t* Ab = sm + bsel*2304;
        uint32_t* Bb = sm + 4608 + bsel*2304;
#pragma unroll
        for (int it = 0; it < 4; it++) {
            int m = mbase + it*16;
            uint4 u = {f2tf(ra[it].x), f2tf(ra[it].y), f2tf(ra[it].z), f2tf(ra[it].w)};
            *(uint4*)&Ab[m*36 + ca] = u;
            int kk = kbase + it*8;
            uint4 w = {f2tf(rb[it].x), f2tf(rb[it].y), f2tf(rb[it].z), f2tf(rb[it].w)};
            *(uint4*)&Bb[kk*72 + cb] = w;
        }
    };

    float acc[2][4][4] = {};
    int ktiles = (K + 31) >> 5;
    load_tile(0);
    sts_tile(0);
    __syncthreads();
    for (int kt = 0; kt < ktiles; kt++) {
        if (kt + 1 < ktiles) load_tile((kt+1) << 5);
        const uint32_t* Ab = sm + (kt&1)*2304;
        const uint32_t* Bb = sm + 4608 + (kt&1)*2304;
#pragma unroll
        for (int k8 = 0; k8 < 4; k8++) {
            int kb = k8 * 8;
            uint32_t a[2][4], bf[4][2];
#pragma unroll
            for (int i = 0; i < 2; i++) {
                int r0 = wm + 16*i + g;
                a[i][0] = Ab[r0*36 + kb + t];
                a[i][1] = Ab[(r0+8)*36 + kb + t];
                a[i][2] = Ab[r0*36 + kb + t + 4];
                a[i][3] = Ab[(r0+8)*36 + kb + t + 4];
            }
#pragma unroll
            for (int j = 0; j < 4; j++) {
                int cn = wn + 8*j + g;
                bf[j][0] = Bb[(kb+t)*72 + cn];
                bf[j][1] = Bb[(kb+t+4)*72 + cn];
            }
#pragma unroll
            for (int i = 0; i < 2; i++)
#pragma unroll
                for (int j = 0; j < 4; j++)
                    mma_tf32(acc[i][j], a[i], bf[j]);
        }
        if (kt + 1 < ktiles) { sts_tile((kt+1)&1); __syncthreads(); }
    }
#pragma unroll
    for (int i = 0; i < 2; i++) {
#pragma unroll
        for (int j = 0; j < 4; j++) {
            int ng = bn + wn + 8*j + 2*t;
            float b0 = bias[ng], b1 = bias[ng+1];
#pragma unroll
            for (int rr = 0; rr < 2; rr++) {
                int mg = bm + wm + 16*i + g + 8*rr;
                float o0 = acc[i][j][rr*2+0] + b0;
                float o1 = acc[i][j][rr*2+1] + b1;
                if (relu) { o0 = fmaxf(o0, 0.f); o1 = fmaxf(o1, 0.f); }
                if (Cres) {
                    float2 rv = *(const float2*)&Cres[(size_t)mg*Nout + ng];
                    o0 += rv.x; o1 += rv.y;
                }
                float2 o = {o0, o1};
                *(float2*)&C[(size_t)mg*Nout + ng] = o;
            }
        }
    }
}

__global__ __launch_bounds__(128) void gemm_mma_kernel(
    const float* __restrict__ A, const float* __restrict__ A2, int K1, int K,
    const float* __restrict__ W, const float* __restrict__ bias,
    float* __restrict__ C, const float* __restrict__ Cres, int Nout, int relu,
    const float* __restrict__ lng, const float* __restrict__ lnb) {
    __shared__ uint32_t sm[9216];   // 2 x (64x36 A + 32x72 B)
    __shared__ float mrow[64], irow[64];
    gemm_mma_core(A, A2, K1, K, W, bias, C, Cres, Nout, relu, lng, lnb, sm, mrow, irow);
}

__global__ __launch_bounds__(128) void gemm3_mma_kernel(const float* __restrict__ A,
                             const float* __restrict__ W0, const float* __restrict__ W1, const float* __restrict__ W2,
                             const float* __restrict__ b0, const float* __restrict__ b1, const float* __restrict__ b2,
                             float* __restrict__ C0, float* __restrict__ C1, float* __restrict__ C2,
                             const float* __restrict__ lng, const float* __restrict__ lnb) {
    __shared__ uint32_t sm[9216];
    __shared__ float mrow[64], irow[64];
    int z = blockIdx.z;
    const float* W = (z == 0) ? W0 : (z == 1) ? W1 : W2;
    const float* b = (z == 0) ? b0 : (z == 1) ? b1 : b2;
    float* C = (z == 0) ? C0 : (z == 1) ? C1 : C2;
    gemm_mma_core(A, A, Dc, Dc, W, b, C, nullptr, Dc, 0, lng, lnb, sm, mrow, irow);
}

// ---------------- v3d with fused LN: warp-per-row LN(x[row]) @ W3 + b3 ----------------
__global__ void v3_kernel(const float* __restrict__ x,
                          const float* __restrict__ lng, const float* __restrict__ lnb,
                          const float* __restrict__ W3, const float* __restrict__ b3,
                          float* __restrict__ out) {
    int warp = (blockIdx.x * blockDim.x + threadIdx.x) >> 5;
    int lane = threadIdx.x & 31;
    if (warp >= Mrows) return;
    const float* xr = x + (size_t)warp*Dc;
    float xv[12];
    float s = 0.f, sq = 0.f;
#pragma unroll
    for (int i = 0; i < 12; i++) {
        float v = xr[lane + i*32];
        xv[i] = v; s += v; sq += v*v;
    }
#pragma unroll
    for (int off = 16; off > 0; off >>= 1) {
        s  += __shfl_xor_sync(0xffffffffu, s, off);
        sq += __shfl_xor_sync(0xffffffffu, sq, off);
    }
    float mean = s * (1.f/384.f);
    float inv = rsqrtf(sq * (1.f/384.f) - mean*mean + 1e-5f);
    float s0 = 0.f, s1 = 0.f, s2 = 0.f;
#pragma unroll
    for (int i = 0; i < 12; i++) {
        int c = lane + i*32;
        float hv = (xv[i] - mean)*inv*lng[c] + lnb[c];
        s0 += hv * W3[c*3+0];
        s1 += hv * W3[c*3+1];
        s2 += hv * W3[c*3+2];
    }
#pragma unroll
    for (int off = 16; off > 0; off >>= 1) {
        s0 += __shfl_down_sync(0xffffffffu, s0, off);
        s1 += __shfl_down_sync(0xffffffffu, s1, off);
        s2 += __shfl_down_sync(0xffffffffu, s2, off);
    }
    if (lane == 0) {
        out[warp*3+0] = s0 + b3[0];
        out[warp*3+1] = s1 + b3[1];
        out[warp*3+2] = s2 + b3[2];
    }
}

// ---------------- combined attention (dynamic smem 58368B) ----------------
// flash (blocks 0..255): separate ks/vs buffers, reg-staged k/v prefetch, 2 syncs/tile.
__device__ void flash_part(uint32_t* dsm,
    const float* __restrict__ q, const float* __restrict__ k, const float* __restrict__ v,
    const float* __restrict__ bias, float* __restrict__ attn_out, int bid)
{
    uint32_t* qs = dsm;              // [q][d]  stride 52 (3328)
    uint32_t* ks = dsm + 3328;       // [k'][d] stride 52 (3328)
    uint32_t* vs = dsm + 6656;       // [k'][d] stride 56 (3584)
    uint32_t* ps = dsm + 10240;      // [q][k'] stride 68 (4352)
    int b = bid >> 7, h = (bid >> 4) & 7, q0 = (bid & 15) * 64;
    int tid = threadIdx.x;
    int warp = tid >> 5, lane = tid & 31;
    int g = lane >> 2, t = lane & 3;
    int wq = warp * 16;

    float4 rk[6], rv[6];
    auto ldg6 = [&](const float* src, int row0, float4* dst) {
#pragma unroll
        for (int j = 0; j < 6; j++) {
            int i = tid + j*128;
            int r = i / 12, c = (i % 12) * 4;
            dst[j] = *(const float4*)&src[(size_t)(b*Nc + row0 + r)*Dc + h*HDc + c];
        }
    };
    auto sts6 = [&](uint32_t* buf, int stride, const float4* src) {
#pragma unroll
        for (int j = 0; j < 6; j++) {
            int i = tid + j*128;
            int r = i / 12, c = (i % 12) * 4;
            buf[r*stride + c]     = f2tf(src[j].x);
            buf[r*stride + c + 1] = f2tf(src[j].y);
            buf[r*stride + c + 2] = f2tf(src[j].z);
            buf[r*stride + c + 3] = f2tf(src[j].w);
        }
    };

    ldg6(q, q0, rk);  sts6(qs, 52, rk);
    ldg6(k, 0, rk);   sts6(ks, 52, rk);
    ldg6(v, 0, rv);
    __syncthreads();

    float O[6][4] = {};
    float rsum0 = 0.f, rsum1 = 0.f;
    const float scale = 0.14433756729740643f;

    for (int kt = 0; kt < 16; kt++) {
        int k0 = kt * 64;
        // ---- S = Q K^T ----
        float sacc[8][4] = {};
#pragma unroll
        for (int d8 = 0; d8 < 6; d8++) {
            uint32_t a[4];
            a[0] = qs[(wq + g)*52 + d8*8 + t];
            a[1] = qs[(wq + g + 8)*52 + d8*8 + t];
            a[2] = qs[(wq + g)*52 + d8*8 + t + 4];
            a[3] = qs[(wq + g + 8)*52 + d8*8 + t + 4];
#pragma unroll
            for (int j = 0; j < 8; j++) {
                uint32_t bb[2];
                bb[0] = ks[(8*j + g)*52 + d8*8 + t];
                bb[1] = ks[(8*j + g)*52 + d8*8 + t + 4];
                mma_tf32(sacc[j], a, bb);
            }
        }
        // ---- epilogue: bias, exp, rsum, ps ----
#pragma unroll
        for (int j = 0; j < 8; j++) {
            int c = 8*j + 2*t;
            size_t row0 = (size_t)(b*Nc + q0 + wq + g);
            float2 d0 = *(const float2*)&bias[row0*Nc + k0 + c];
            float2 d1 = *(const float2*)&bias[(row0 + 8)*Nc + k0 + c];
            float e00 = __expf(sacc[j][0]*scale + d0.x);
            float e01 = __expf(sacc[j][1]*scale + d0.y);
            float e10 = __expf(sacc[j][2]*scale + d1.x);
            float e11 = __expf(sacc[j][3]*scale + d1.y);
            rsum0 += e00 + e01; rsum1 += e10 + e11;
            ps[(wq + g)*68 + c]         = f2tf(e00);
            ps[(wq + g)*68 + c + 1]     = f2tf(e01);
            ps[(wq + g + 8)*68 + c]     = f2tf(e10);
            ps[(wq + g + 8)*68 + c + 1] = f2tf(e11);
        }
        sts6(vs, 56, rv);                        // v(kt) into vs
        if (kt < 15) ldg6(k, k0 + 64, rk);       // prefetch k(kt+1)
        __syncthreads();                         // ps+vs ready; QK reads of ks done
        // ---- O += P V ----
#pragma unroll
        for (int j8 = 0; j8 < 8; j8++) {
            uint32_t a[4];
            a[0] = ps[(wq + g)*68 + 8*j8 + t];
            a[1] = ps[(wq + g + 8)*68 + 8*j8 + t];
            a[2] = ps[(wq + g)*68 + 8*j8 + t + 4];
            a[3] = ps[(wq + g + 8)*68 + 8*j8 + t + 4];
#pragma unroll
            for (int dn = 0; dn < 6; dn++) {
                uint32_t bb[2];
                bb[0] = vs[(8*j8 + t)*56 + 8*dn + g];
                bb[1] = vs[(8*j8 + t + 4)*56 + 8*dn + g];
                mma_tf32(O[dn], a, bb);
            }
        }
        if (kt < 15) {
            sts6(ks, 52, rk);                    // k(kt+1) into ks (PV doesn't read ks)
            ldg6(v, k0 + 64, rv);                // prefetch v(kt+1)
            __syncthreads();                     // PV reads done before next ps/vs writes
        }
    }
#pragma unroll
    for (int off = 1; off <= 2; off <<= 1) {
        rsum0 += __shfl_xor_sync(0xffffffffu, rsum0, off);
        rsum1 += __shfl_xor_sync(0xffffffffu, rsum1, off);
    }
    float rinv0 = 1.f / rsum0, rinv1 = 1.f / rsum1;
#pragma unroll
    for (int dn = 0; dn < 6; dn++) {
        int c = 8*dn + 2*t;
        float2 o0 = {O[dn][0]*rinv0, O[dn][1]*rinv0};
        float2 o1 = {O[dn][2]*rinv1, O[dn][3]*rinv1};
        *(float2*)&attn_out[(size_t)(b*Nc + q0 + wq + g)*Dc + h*HDc + c]     = o0;
        *(float2*)&attn_out[(size_t)(b*Nc + q0 + wq + g + 8)*Dc + h*HDc + c] = o1;
    }
}

// qkfull (blocks 256..767): reg-staged prefetch of next 64-dim chunk.
__device__ void qkfull_part(uint32_t* dsm,
    const float* __restrict__ q, const float* __restrict__ k,
    const float* __restrict__ bias, float* __restrict__ mlog, int qid)
{
    uint32_t* qs = dsm;            // [q][64] stride 68
    uint32_t* ks = dsm + 4352;
    int b = qid >> 8, q0 = ((qid >> 4) & 15) * 64, k0 = (qid & 15) * 64;
    int tid = threadIdx.x;
    int warp = tid >> 5, lane = tid & 31;
    int g = lane >> 2, t = lane & 3;
    int wq = warp * 16;

    float4 rq[8], rk2[8];
    auto ldg8 = [&](int d0) {
#pragma unroll
        for (int j = 0; j < 8; j++) {
            int i = tid + j*128;
            int r = i >> 4, c = (i & 15) * 4;
            rq[j]  = *(const float4*)&q[(size_t)(b*Nc + q0 + r)*Dc + d0 + c];
            rk2[j] = *(const float4*)&k[(size_t)(b*Nc + k0 + r)*Dc + d0 + c];
        }
    };
    auto sts8 = [&]() {
#pragma unroll
        for (int j = 0; j < 8; j++) {
            int i = tid + j*128;
            int r = i >> 4, c = (i & 15) * 4;
            qs[r*68+c] = f2tf(rq[j].x); qs[r*68+c+1] = f2tf(rq[j].y);
            qs[r*68+c+2] = f2tf(rq[j].z); qs[r*68+c+3] = f2tf(rq[j].w);
            ks[r*68+c] = f2tf(rk2[j].x); ks[r*68+c+1] = f2tf(rk2[j].y);
            ks[r*68+c+2] = f2tf(rk2[j].z); ks[r*68+c+3] = f2tf(rk2[j].w);
        }
    };

    ldg8(0); sts8();
    __syncthreads();
    float sacc[8][4] = {};
    for (int dt = 0; dt < 6; dt++) {
        if (dt < 5) ldg8((dt+1) * 64);
#pragma unroll
        for (int d8 = 0; d8 < 8; d8++) {
            uint32_t a[4];
            a[0] = qs[(wq + g)*68 + d8*8 + t];
            a[1] = qs[(wq + g + 8)*68 + d8*8 + t];
            a[2] = qs[(wq + g)*68 + d8*8 + t + 4];
            a[3] = qs[(wq + g + 8)*68 + d8*8 + t + 4];
#pragma unroll
            for (int j = 0; j < 8; j++) {
                uint32_t bb[2];
                bb[0] = ks[(8*j + g)*68 + d8*8 + t];
                bb[1] = ks[(8*j + g)*68 + d8*8 + t + 4];
                mma_tf32(sacc[j], a, bb);
            }
        }
        if (dt < 5) {
            __syncthreads();   // all MMA reads of current chunk done
            sts8();
            __syncthreads();   // next chunk visible
        }
    }
    const float scale = 0.14433756729740643f;
#pragma unroll
    for (int j = 0; j < 8; j++) {
        int c = 8*j + 2*t;
        size_t row0 = (size_t)(b*Nc + q0 + wq + g);
        float2 d0 = *(const float2*)&bias[row0*Nc + k0 + c];
        float2 d1 = *(const float2*)&bias[(row0 + 8)*Nc + k0 + c];
        float2 w0 = {sacc[j][0]*scale + 8.f*d0.x, sacc[j][1]*scale + 8.f*d0.y};
        float2 w1 = {sacc[j][2]*scale + 8.f*d1.x, sacc[j][3]*scale + 8.f*d1.y};
        *(float2*)&mlog[row0*Nc + k0 + c]       = w0;
        *(float2*)&mlog[(row0 + 8)*Nc + k0 + c] = w1;
    }
}

__global__ __launch_bounds__(128) void attn_kernel(
    const float* __restrict__ q, const float* __restrict__ k, const float* __restrict__ v,
    const float* __restrict__ bias, float* __restrict__ attn_out, float* __restrict__ mlog)
{
    extern __shared__ uint32_t dsm[];
    int bx = blockIdx.x;
    if (bx < 256) flash_part(dsm, q, k, v, bias, attn_out, bx);
    else          qkfull_part(dsm, q, k, bias, mlog, bx - 256);
}

#define ATTN_SMEM (14592 * 4)   // qs+ks+vs+ps for flash = 58368 B

// ---------------- merged softmax + geometric frame (fused, reads mlogits) ----------------
__global__ void merged_frame_kernel(const float* __restrict__ mlog,
                                    const float* __restrict__ ad, const float* __restrict__ S,
                                    const float* __restrict__ v3d, float* __restrict__ frame) {
    int row = blockIdx.x;          // b*N + i
    int b = row >> 10;
    int tid = threadIdx.x;         // 256
    __shared__ float probs[Nc];
    __shared__ float v3s[Nc*3];
    __shared__ float sh[256];
    for (int tn = tid; tn < 768; tn += 256)
        *(float4*)&v3s[tn*4] = *(const float4*)&v3d[b*Nc*3 + tn*4];
    float4 lv = *(const float4*)&mlog[(size_t)row*Nc + tid*4];
    float e0 = __expf(lv.x), e1 = __expf(lv.y), e2 = __expf(lv.z), e3 = __expf(lv.w);
    sh[tid] = e0 + e1 + e2 + e3; __syncthreads();
    for (int st = 128; st > 0; st >>= 1) {
        if (tid < st) sh[tid] += sh[tid+st];
        __syncthreads();
    }
    float inv = 1.f / sh[0];
    float4 pr = {e0*inv, e1*inv, e2*inv, e3*inv};
    *(float4*)&probs[tid*4] = pr;
    __syncthreads();
    float cx = 0.f, cy = 0.f, cz = 0.f;
    {
        int j0 = tid * 4;
        size_t base = ((size_t)row*Nc + j0)*3;
        float4 A0 = *(const float4*)&ad[base];
        float4 A1 = *(const float4*)&ad[base+4];
        float4 A2 = *(const float4*)&ad[base+8];
        float4 S0 = *(const float4*)&S[base];
        float4 S1 = *(const float4*)&S[base+4];
        float4 S2 = *(const float4*)&S[base+8];
        float af[12] = {A0.x,A0.y,A0.z,A0.w,A1.x,A1.y,A1.z,A1.w,A2.x,A2.y,A2.z,A2.w};
        float sf[12] = {S0.x,S0.y,S0.z,S0.w,S1.x,S1.y,S1.z,S1.w,S2.x,S2.y,S2.z,S2.w};
#pragma unroll
        for (int jj = 0; jj < 4; jj++) {
            int j = j0 + jj;
            float m = probs[j];
            float ax = af[jj*3+0], ay = af[jj*3+1], az = af[jj*3+2];
            float bx = sf[jj*3+0]*v3s[j*3+0];
            float by = sf[jj*3+1]*v3s[j*3+1];
            float bz = sf[jj*3+2]*v3s[j*3+2];
            cx += m * (ay*bz - az*by);
            cy += m * (az*bx - ax*bz);
            cz += m * (ax*by - ay*bx);
        }
    }
    float vals[3] = {cx, cy, cz};
#pragma unroll
    for (int c = 0; c < 3; c++) {
        sh[tid] = vals[c]; __syncthreads();
        for (int st = 128; st > 0; st >>= 1) {
            if (tid < st) sh[tid] += sh[tid+st];
            __syncthreads();
        }
        if (tid == 0) frame[row*3 + c] = sh[0] * (1.f/Nc);
        __syncthreads();
    }
}

// ---------------- host driver ----------------
extern "C" void kernel_launch(void* const* d_in, const int* in_sizes, int n_in,
                              void* d_out, int out_size) {
    const float* x_rigid = (const float*)d_in[0];
    const float* ad      = (const float*)d_in[1];
    const float* orient  = (const float*)d_in[2];
    const float* dist    = (const float*)d_in[3];
    const int*   amask   = (const int*)  d_in[4];
    const float* Wq   = (const float*)d_in[5];
    const float* bq   = (const float*)d_in[6];
    const float* Wk   = (const float*)d_in[7];
    const float* bk   = (const float*)d_in[8];
    const float* Wv   = (const float*)d_in[9];
    const float* bv   = (const float*)d_in[10];
    const float* W3   = (const float*)d_in[11];
    const float* b3   = (const float*)d_in[12];
    const float* Wmlp = (const float*)d_in[13];
    const float* bmlp = (const float*)d_in[14];
    const float* Wfc  = (const float*)d_in[15];
    const float* bfc  = (const float*)d_in[16];
    const float* Wff1 = (const float*)d_in[17];
    const float* bff1 = (const float*)d_in[18];
    const float* Wff2 = (const float*)d_in[19];
    const float* bff2 = (const float*)d_in[20];
    const float* ln1g = (const float*)d_in[21];
    const float* ln1b = (const float*)d_in[22];
    const float* ln2g = (const float*)d_in[23];
    const float* ln2b = (const float*)d_in[24];

    float *px, *pq, *pk, *pv, *pav, *pml, *pS, *pbias, *pv3, *pfr, *pff;
    cudaGetSymbolAddress((void**)&px,  g_x);
    cudaGetSymbolAddress((void**)&pq,  g_q);
    cudaGetSymbolAddress((void**)&pk,  g_k);
    cudaGetSymbolAddress((void**)&pv,  g_v);
    cudaGetSymbolAddress((void**)&pav, g_attnv);
    cudaGetSymbolAddress((void**)&pml, g_mlogits);
    cudaGetSymbolAddress((void**)&pS,  g_S);
    cudaGetSymbolAddress((void**)&pbias, g_bias);
    cudaGetSymbolAddress((void**)&pv3, g_v3d);
    cudaGetSymbolAddress((void**)&pfr, g_frame);
    cudaGetSymbolAddress((void**)&pff, g_ff);

    cudaFuncSetAttribute(attn_kernel, cudaFuncAttributeMaxDynamicSharedMemorySize, ATTN_SMEM);

    precomp_S<<<(BNN+255)/256, 256>>>(orient, pS);
    table_kernel<<<(Lc*(TBL+1)+255)/256, 256>>>(Wmlp, bmlp);
    bias_kernel<<<(BNN+255)/256, 256>>>(dist, amask, pbias);

    dim3 gQKV3(Dc/64, Mrows/64, 3);   // (6,32,3)
    dim3 gFC(Dc/64, Mrows/64);        // (6,32)
    dim3 gFF1(DFFc/64, Mrows/64);     // (8,32)

    for (int l = 0; l < Lc; l++) {
        const float* xin = (l == 0) ? x_rigid : px;
        float* ff2out = (l == Lc-1) ? (float*)d_out : px;
        gemm3_mma_kernel<<<gQKV3, 128>>>(xin, Wq + l*Dc*Dc, Wk + l*Dc*Dc, Wv + l*Dc*Dc,
                                         bq + l*Dc, bk + l*Dc, bv + l*Dc, pq, pk, pv,
                                         ln1g + l*Dc, ln1b + l*Dc);
        v3_kernel<<<Mrows/8, 256>>>(xin, ln1g + l*Dc, ln1b + l*Dc, W3 + l*Dc*3, b3 + l*3, pv3);
        attn_kernel<<<768, 128, ATTN_SMEM>>>(pq, pk, pv, pbias + (size_t)l*BNN, pav, pml);
        merged_frame_kernel<<<Mrows, 256>>>(pml, ad, pS, pv3, pfr);
        gemm_mma_kernel<<<gFC, 128>>>(pav, pfr, Dc, Dc+3, Wfc + l*(Dc+3)*Dc, bfc + l*Dc,
                                      px, xin, Dc, 0, nullptr, nullptr);
        gemm_mma_kernel<<<gFF1, 128>>>(px, px, Dc, Dc, Wff1 + l*Dc*DFFc, bff1 + l*DFFc,
                                       pff, nullptr, DFFc, 1, ln2g + l*Dc, ln2b + l*Dc);
        gemm_mma_kernel<<<gFC, 128>>>(pff, pff, DFFc, DFFc, Wff2 + l*DFFc*Dc, bff2 + l*Dc,
                                      ff2out, px, Dc, 0, nullptr, nullptr);
    }
}

// round 13
// speedup vs baseline: 1.6294x; 1.2126x over previous
#include <cuda_runtime.h>
#include <math.h>
#include <stdint.h>

#define Bc 2
#define Nc 1024
#define Dc 384
#define Hc 8
#define HDc 48
#define DFFc 512
#define Lc 4
#define Mrows (Bc*Nc)        // 2048
#define BNN (Bc*Nc*Nc)
#define TBL 4096

// ---------------- scratch ----------------
__device__ float g_x[Bc*Nc*Dc];
__device__ float g_h[Bc*Nc*Dc];
__device__ float g_q[Bc*Nc*Dc];
__device__ float g_k[Bc*Nc*Dc];
__device__ float g_v[Bc*Nc*Dc];
__device__ float g_attnv[Bc*Nc*Dc];
__device__ float g_mlogits[BNN];                  // 8 MB merged logits
__device__ float g_S[Bc*Nc*Nc*3];                 // 24 MB colsum_m(orientation)
__device__ float g_bias[(size_t)Lc*BNN];          // 32 MB dis-bias (mask folded)
__device__ float g_tbl[Lc][TBL+1];
__device__ float g_v3d[Mrows*3];
__device__ float g_frame[Mrows*3];
__device__ float g_ff[Mrows*DFFc];

// ---------------- helpers ----------------
__device__ __forceinline__ void mma_tf32(float d[4], const uint32_t a[4], const uint32_t b[2]) {
    asm volatile("mma.sync.aligned.m16n8k8.row.col.f32.tf32.tf32.f32 "
        "{%0,%1,%2,%3}, {%4,%5,%6,%7}, {%8,%9}, {%0,%1,%2,%3};"
        : "+f"(d[0]), "+f"(d[1]), "+f"(d[2]), "+f"(d[3])
        : "r"(a[0]), "r"(a[1]), "r"(a[2]), "r"(a[3]), "r"(b[0]), "r"(b[1]));
}
__device__ __forceinline__ void cp16(uint32_t saddr, const void* g) {
    asm volatile("cp.async.cg.shared.global [%0], [%1], 16;" :: "r"(saddr), "l"(g) : "memory");
}
__device__ __forceinline__ void cp_commit() {
    asm volatile("cp.async.commit_group;" ::: "memory");
}
__device__ __forceinline__ void cp_wait1() {
    asm volatile("cp.async.wait_group 1;" ::: "memory");
}
__device__ __forceinline__ void cp_wait0() {
    asm volatile("cp.async.wait_group 0;" ::: "memory");
}

// ---------------- S[b,i,j,n] = sum_m orientation[b,i,j,m,n] ----------------
__global__ void precomp_S(const float* __restrict__ orient, float* __restrict__ S) {
    int idx = blockIdx.x * blockDim.x + threadIdx.x;
    if (idx >= BNN) return;
    const float* o = orient + (size_t)idx * 9;
    S[idx*3+0] = o[0] + o[3] + o[6];
    S[idx*3+1] = o[1] + o[4] + o[7];
    S[idx*3+2] = o[2] + o[5] + o[8];
}

// ---------------- per-layer RBF bias lookup table ----------------
__global__ void table_kernel(const float* __restrict__ Wmlp, const float* __restrict__ bmlp) {
    int i = blockIdx.x * blockDim.x + threadIdx.x;
    if (i >= Lc*(TBL+1)) return;
    int l = i / (TBL+1), t = i % (TBL+1);
    float d = 20.f * (float)t / (float)TBL;
    float acc = bmlp[l];
    const float invsig = 0.8f;
#pragma unroll
    for (int r = 0; r < 16; r++) {
        float mu = (20.f/15.f) * (float)r;
        float u = (d - mu) * invsig;
        acc += Wmlp[l*16 + r] * expf(-u*u);
    }
    g_tbl[l][t] = acc;
}

// ---------------- bias_all[l][p] = mask? -1e9 : lerp(table_l, dist[p]) ----------------
__global__ void bias_kernel(const float* __restrict__ dist, const int* __restrict__ mask,
                            float* __restrict__ bias_all) {
    int p = blockIdx.x * blockDim.x + threadIdx.x;
    if (p >= BNN) return;
    float d = dist[p];
    bool m0 = (mask[p] == 0);
    float fi = fmaxf(d, 0.f) * ((float)TBL / 20.f);
    int i0 = min((int)fi, TBL-1);
    float fr = fi - (float)i0;
#pragma unroll
    for (int l = 0; l < Lc; l++) {
        float t0 = g_tbl[l][i0], t1 = g_tbl[l][i0+1];
        float v = t0 + fr * (t1 - t0);
        bias_all[(size_t)l*BNN + p] = m0 ? -1e9f : v;
    }
}

// ---------------- LayerNorm ----------------
__global__ void ln_kernel(const float* __restrict__ x, const float* __restrict__ g,
                          const float* __restrict__ b, float* __restrict__ out) {
    int row = blockIdx.x;
    const float* xr = x + (size_t)row*Dc;
    float v[3];
    float s = 0.f, s2 = 0.f;
#pragma unroll
    for (int i = 0; i < 3; i++) {
        v[i] = xr[threadIdx.x + i*128];
        s += v[i]; s2 += v[i]*v[i];
    }
    __shared__ float sh1[128], sh2[128];
    sh1[threadIdx.x] = s; sh2[threadIdx.x] = s2;
    __syncthreads();
    for (int st = 64; st > 0; st >>= 1) {
        if (threadIdx.x < st) { sh1[threadIdx.x] += sh1[threadIdx.x+st]; sh2[threadIdx.x] += sh2[threadIdx.x+st]; }
        __syncthreads();
    }
    float mean = sh1[0] * (1.f/Dc);
    float var  = sh2[0] * (1.f/Dc) - mean*mean;
    float inv  = rsqrtf(var + 1e-5f);
#pragma unroll
    for (int i = 0; i < 3; i++) {
        int c = threadIdx.x + i*128;
        out[(size_t)row*Dc + c] = (v[i] - mean) * inv * g[c] + b[c];
    }
}

// ---------------- TF32 MMA GEMM: 64x64 tile, BK=32, cp.async double buffer ----------------
// K must be a multiple of 32. Optional rank-3 tail: C += tailA[m,0:3] @ tailW[0:3, n].
__device__ __forceinline__ void gemm_mma_core(
    const float* __restrict__ A, int K,
    const float* __restrict__ W, const float* __restrict__ bias,
    float* __restrict__ C, const float* __restrict__ Cres, int Nout, int relu,
    const float* __restrict__ tailA, const float* __restrict__ tailW,
    uint32_t* sm)
{
    int bm = blockIdx.y * 64, bn = blockIdx.x * 64;
    int tid = threadIdx.x;
    int warp = tid >> 5, lane = tid & 31;
    int wm = (warp & 1) * 32, wn = (warp >> 1) * 32;
    int g = lane >> 2, t = lane & 3;
    uint32_t sbase = (uint32_t)__cvta_generic_to_shared(sm);
    int ktiles = K >> 5;

    // smem layout (words): A0[0,2304) A1[2304,4608) B0[4608,6912) B1[6912,9216)
    auto issue_tile = [&](int kt) {
        int k0 = kt << 5;
        uint32_t Ab = sbase + (kt & 1) * 9216;
        uint32_t Bb = sbase + 18432 + (kt & 1) * 9216;
#pragma unroll
        for (int it = 0; it < 4; it++) {
            int idx = tid + it*128;
            int m = idx >> 3, ca4 = (idx & 7) * 4;
            cp16(Ab + (m*36 + ca4)*4, A + (size_t)(bm+m)*K + k0 + ca4);
            int kk = idx >> 4, cb4 = (idx & 15) * 4;
            cp16(Bb + (kk*72 + cb4)*4, W + (size_t)(k0+kk)*Nout + bn + cb4);
        }
        cp_commit();
    };

    float acc[2][4][4] = {};
    issue_tile(0);
    for (int kt = 0; kt < ktiles; kt++) {
        if (kt + 1 < ktiles) { issue_tile(kt+1); cp_wait1(); }
        else cp_wait0();
        __syncthreads();
        const uint32_t* Ab = sm + (kt & 1) * 2304;
        const uint32_t* Bb = sm + 4608 + (kt & 1) * 2304;
#pragma unroll
        for (int k8 = 0; k8 < 4; k8++) {
            int kb = k8 * 8;
            uint32_t a[2][4], bf[4][2];
#pragma unroll
            for (int i = 0; i < 2; i++) {
                int r0 = wm + 16*i + g;
                a[i][0] = Ab[r0*36 + kb + t];
                a[i][1] = Ab[(r0+8)*36 + kb + t];
                a[i][2] = Ab[r0*36 + kb + t + 4];
                a[i][3] = Ab[(r0+8)*36 + kb + t + 4];
            }
#pragma unroll
            for (int j = 0; j < 4; j++) {
                int cn = wn + 8*j + g;
                bf[j][0] = Bb[(kb+t)*72 + cn];
                bf[j][1] = Bb[(kb+t+4)*72 + cn];
            }
#pragma unroll
            for (int i = 0; i < 2; i++)
#pragma unroll
                for (int j = 0; j < 4; j++)
                    mma_tf32(acc[i][j], a[i], bf[j]);
        }
        __syncthreads();
    }
#pragma unroll
    for (int j = 0; j < 4; j++) {
        int ng = bn + wn + 8*j + 2*t;
        float b0 = bias[ng], b1 = bias[ng+1];
        float tw[3][2];
        if (tailA) {
#pragma unroll
            for (int r = 0; r < 3; r++) {
                tw[r][0] = __ldg(&tailW[r*Nout + ng]);
                tw[r][1] = __ldg(&tailW[r*Nout + ng + 1]);
            }
        }
#pragma unroll
        for (int i = 0; i < 2; i++) {
#pragma unroll
            for (int rr = 0; rr < 2; rr++) {
                int mg = bm + wm + 16*i + g + 8*rr;
                float o0 = acc[i][j][rr*2+0] + b0;
                float o1 = acc[i][j][rr*2+1] + b1;
                if (tailA) {
                    float f0 = __ldg(&tailA[mg*3]), f1 = __ldg(&tailA[mg*3+1]), f2 = __ldg(&tailA[mg*3+2]);
                    o0 += f0*tw[0][0] + f1*tw[1][0] + f2*tw[2][0];
                    o1 += f0*tw[0][1] + f1*tw[1][1] + f2*tw[2][1];
                }
                if (relu) { o0 = fmaxf(o0, 0.f); o1 = fmaxf(o1, 0.f); }
                if (Cres) {
                    float2 rv = *(const float2*)&Cres[(size_t)mg*Nout + ng];
                    o0 += rv.x; o1 += rv.y;
                }
                float2 o = {o0, o1};
                *(float2*)&C[(size_t)mg*Nout + ng] = o;
            }
        }
    }
}

__global__ __launch_bounds__(128) void gemm_mma_kernel(
    const float* __restrict__ A, int K,
    const float* __restrict__ W, const float* __restrict__ bias,
    float* __restrict__ C, const float* __restrict__ Cres, int Nout, int relu,
    const float* __restrict__ tailA, const float* __restrict__ tailW) {
    __shared__ uint32_t sm[9216];
    gemm_mma_core(A, K, W, bias, C, Cres, Nout, relu, tailA, tailW, sm);
}

__global__ __launch_bounds__(128) void gemm3_mma_kernel(const float* __restrict__ A,
                             const float* __restrict__ W0, const float* __restrict__ W1, const float* __restrict__ W2,
                             const float* __restrict__ b0, const float* __restrict__ b1, const float* __restrict__ b2,
                             float* __restrict__ C0, float* __restrict__ C1, float* __restrict__ C2) {
    __shared__ uint32_t sm[9216];
    int z = blockIdx.z;
    const float* W = (z == 0) ? W0 : (z == 1) ? W1 : W2;
    const float* b = (z == 0) ? b0 : (z == 1) ? b1 : b2;
    float* C = (z == 0) ? C0 : (z == 1) ? C1 : C2;
    gemm_mma_core(A, Dc, W, b, C, nullptr, Dc, 0, nullptr, nullptr, sm);
}

// ---------------- v3d: warp-per-row h[row] @ W3 + b3 ----------------
__global__ void v3_kernel(const float* __restrict__ h, const float* __restrict__ W3,
                          const float* __restrict__ b3, float* __restrict__ out) {
    int warp = (blockIdx.x * blockDim.x + threadIdx.x) >> 5;
    int lane = threadIdx.x & 31;
    if (warp >= Mrows) return;
    const float* hr = h + (size_t)warp*Dc;
    float s0 = 0.f, s1 = 0.f, s2 = 0.f;
#pragma unroll
    for (int i = 0; i < 12; i++) {
        int c = lane + i*32;
        float hv = hr[c];
        s0 += hv * W3[c*3+0];
        s1 += hv * W3[c*3+1];
        s2 += hv * W3[c*3+2];
    }
#pragma unroll
    for (int off = 16; off > 0; off >>= 1) {
        s0 += __shfl_down_sync(0xffffffffu, s0, off);
        s1 += __shfl_down_sync(0xffffffffu, s1, off);
        s2 += __shfl_down_sync(0xffffffffu, s2, off);
    }
    if (lane == 0) {
        out[warp*3+0] = s0 + b3[0];
        out[warp*3+1] = s1 + b3[1];
        out[warp*3+2] = s2 + b3[2];
    }
}

// ---------------- combined attention ----------------
// flash (blocks 0..255): reg-staged k/v prefetch (raw fp32 bits into smem; MMA rounds to tf32)
__device__ void flash_part(uint32_t* dsm,
    const float* __restrict__ q, const float* __restrict__ k, const float* __restrict__ v,
    const float* __restrict__ bias, float* __restrict__ attn_out, int bid)
{
    uint32_t* qs = dsm;              // [q][d]  stride 52
    uint32_t* ks = dsm + 3328;       // [k'][d] stride 52
    uint32_t* vs = dsm + 6656;       // [k'][d] stride 56
    uint32_t* ps = dsm + 10240;      // [q][k'] stride 68
    int b = bid >> 7, h = (bid >> 4) & 7, q0 = (bid & 15) * 64;
    int tid = threadIdx.x;
    int warp = tid >> 5, lane = tid & 31;
    int g = lane >> 2, t = lane & 3;
    int wq = warp * 16;

    float4 rk[6], rv[6];
    auto ldg6 = [&](const float* src, int row0, float4* dst) {
#pragma unroll
        for (int j = 0; j < 6; j++) {
            int i = tid + j*128;
            int r = i / 12, c = (i % 12) * 4;
            dst[j] = *(const float4*)&src[(size_t)(b*Nc + row0 + r)*Dc + h*HDc + c];
        }
    };
    auto sts6 = [&](uint32_t* buf, int stride, const float4* src) {
#pragma unroll
        for (int j = 0; j < 6; j++) {
            int i = tid + j*128;
            int r = i / 12, c = (i % 12) * 4;
            buf[r*stride + c]     = __float_as_uint(src[j].x);
            buf[r*stride + c + 1] = __float_as_uint(src[j].y);
            buf[r*stride + c + 2] = __float_as_uint(src[j].z);
            buf[r*stride + c + 3] = __float_as_uint(src[j].w);
        }
    };

    ldg6(q, q0, rk);  sts6(qs, 52, rk);
    ldg6(k, 0, rk);   sts6(ks, 52, rk);
    ldg6(v, 0, rv);
    __syncthreads();

    float O[6][4] = {};
    float rsum0 = 0.f, rsum1 = 0.f;
    const float scale = 0.14433756729740643f;

    for (int kt = 0; kt < 16; kt++) {
        int k0 = kt * 64;
        float sacc[8][4] = {};
#pragma unroll
        for (int d8 = 0; d8 < 6; d8++) {
            uint32_t a[4];
            a[0] = qs[(wq + g)*52 + d8*8 + t];
            a[1] = qs[(wq + g + 8)*52 + d8*8 + t];
            a[2] = qs[(wq + g)*52 + d8*8 + t + 4];
            a[3] = qs[(wq + g + 8)*52 + d8*8 + t + 4];
#pragma unroll
            for (int j = 0; j < 8; j++) {
                uint32_t bb[2];
                bb[0] = ks[(8*j + g)*52 + d8*8 + t];
                bb[1] = ks[(8*j + g)*52 + d8*8 + t + 4];
                mma_tf32(sacc[j], a, bb);
            }
        }
#pragma unroll
        for (int j = 0; j < 8; j++) {
            int c = 8*j + 2*t;
            size_t row0 = (size_t)(b*Nc + q0 + wq + g);
            float2 d0 = *(const float2*)&bias[row0*Nc + k0 + c];
            float2 d1 = *(const float2*)&bias[(row0 + 8)*Nc + k0 + c];
            float e00 = __expf(sacc[j][0]*scale + d0.x);
            float e01 = __expf(sacc[j][1]*scale + d0.y);
            float e10 = __expf(sacc[j][2]*scale + d1.x);
            float e11 = __expf(sacc[j][3]*scale + d1.y);
            rsum0 += e00 + e01; rsum1 += e10 + e11;
            ps[(wq + g)*68 + c]         = __float_as_uint(e00);
            ps[(wq + g)*68 + c + 1]     = __float_as_uint(e01);
            ps[(wq + g + 8)*68 + c]     = __float_as_uint(e10);
            ps[(wq + g + 8)*68 + c + 1] = __float_as_uint(e11);
        }
        sts6(vs, 56, rv);
        if (kt < 15) ldg6(k, k0 + 64, rk);
        __syncthreads();
#pragma unroll
        for (int j8 = 0; j8 < 8; j8++) {
            uint32_t a[4];
            a[0] = ps[(wq + g)*68 + 8*j8 + t];
            a[1] = ps[(wq + g + 8)*68 + 8*j8 + t];
            a[2] = ps[(wq + g)*68 + 8*j8 + t + 4];
            a[3] = ps[(wq + g + 8)*68 + 8*j8 + t + 4];
#pragma unroll
            for (int dn = 0; dn < 6; dn++) {
                uint32_t bb[2];
                bb[0] = vs[(8*j8 + t)*56 + 8*dn + g];
                bb[1] = vs[(8*j8 + t + 4)*56 + 8*dn + g];
                mma_tf32(O[dn], a, bb);
            }
        }
        if (kt < 15) {
            sts6(ks, 52, rk);
            ldg6(v, k0 + 64, rv);
            __syncthreads();
        }
    }
#pragma unroll
    for (int off = 1; off <= 2; off <<= 1) {
        rsum0 += __shfl_xor_sync(0xffffffffu, rsum0, off);
        rsum1 += __shfl_xor_sync(0xffffffffu, rsum1, off);
    }
    float rinv0 = 1.f / rsum0, rinv1 = 1.f / rsum1;
#pragma unroll
    for (int dn = 0; dn < 6; dn++) {
        int c = 8*dn + 2*t;
        float2 o0 = {O[dn][0]*rinv0, O[dn][1]*rinv0};
        float2 o1 = {O[dn][2]*rinv1, O[dn][3]*rinv1};
        *(float2*)&attn_out[(size_t)(b*Nc + q0 + wq + g)*Dc + h*HDc + c]     = o0;
        *(float2*)&attn_out[(size_t)(b*Nc + q0 + wq + g + 8)*Dc + h*HDc + c] = o1;
    }
}

// qkfull (blocks 256..767): cp.async double-buffered 64-dim chunks
__device__ void qkfull_part(uint32_t* dsm,
    const float* __restrict__ q, const float* __restrict__ k,
    const float* __restrict__ bias, float* __restrict__ mlog, int qid)
{
    // words: qs0 0, ks0 4352, qs1 8704, ks1 13056 (stride 68)
    int b = qid >> 8, q0 = ((qid >> 4) & 15) * 64, k0 = (qid & 15) * 64;
    int tid = threadIdx.x;
    int warp = tid >> 5, lane = tid & 31;
    int g = lane >> 2, t = lane & 3;
    int wq = warp * 16;
    uint32_t sbase = (uint32_t)__cvta_generic_to_shared(dsm);

    auto issue = [&](int dt) {
        int d0 = dt * 64;
        uint32_t qb = sbase + ((dt & 1) ? 8704u*4u : 0u);
        uint32_t kb = qb + 4352u*4u;
#pragma unroll
        for (int it = 0; it < 8; it++) {
            int idx = tid + it*128;
            int r = idx >> 4, c4 = (idx & 15) * 4;
            cp16(qb + (r*68 + c4)*4, q + (size_t)(b*Nc + q0 + r)*Dc + d0 + c4);
            cp16(kb + (r*68 + c4)*4, k + (size_t)(b*Nc + k0 + r)*Dc + d0 + c4);
        }
        cp_commit();
    };

    float sacc[8][4] = {};
    issue(0);
    for (int dt = 0; dt < 6; dt++) {
        if (dt + 1 < 6) { issue(dt+1); cp_wait1(); }
        else cp_wait0();
        __syncthreads();
        const uint32_t* qs = dsm + (dt & 1) * 8704;
        const uint32_t* ks = qs + 4352;
#pragma unroll
        for (int d8 = 0; d8 < 8; d8++) {
            uint32_t a[4];
            a[0] = qs[(wq + g)*68 + d8*8 + t];
            a[1] = qs[(wq + g + 8)*68 + d8*8 + t];
            a[2] = qs[(wq + g)*68 + d8*8 + t + 4];
            a[3] = qs[(wq + g + 8)*68 + d8*8 + t + 4];
#pragma unroll
            for (int j = 0; j < 8; j++) {
                uint32_t bb[2];
                bb[0] = ks[(8*j + g)*68 + d8*8 + t];
                bb[1] = ks[(8*j + g)*68 + d8*8 + t + 4];
                mma_tf32(sacc[j], a, bb);
            }
        }
        __syncthreads();
    }
    const float scale = 0.14433756729740643f;
#pragma unroll
    for (int j = 0; j < 8; j++) {
        int c = 8*j + 2*t;
        size_t row0 = (size_t)(b*Nc + q0 + wq + g);
        float2 d0 = *(const float2*)&bias[row0*Nc + k0 + c];
        float2 d1 = *(const float2*)&bias[(row0 + 8)*Nc + k0 + c];
        float2 w0 = {sacc[j][0]*scale + 8.f*d0.x, sacc[j][1]*scale + 8.f*d0.y};
        float2 w1 = {sacc[j][2]*scale + 8.f*d1.x, sacc[j][3]*scale + 8.f*d1.y};
        *(float2*)&mlog[row0*Nc + k0 + c]       = w0;
        *(float2*)&mlog[(row0 + 8)*Nc + k0 + c] = w1;
    }
}

__global__ __launch_bounds__(128) void attn_kernel(
    const float* __restrict__ q, const float* __restrict__ k, const float* __restrict__ v,
    const float* __restrict__ bias, float* __restrict__ attn_out, float* __restrict__ mlog)
{
    extern __shared__ uint32_t dsm[];
    int bx = blockIdx.x;
    if (bx < 256) flash_part(dsm, q, k, v, bias, attn_out, bx);
    else          qkfull_part(dsm, q, k, bias, mlog, bx - 256);
}

#define ATTN_SMEM (17408 * 4)   // qkfull double buffer = 69632 B (flash uses 58368)

// ---------------- merged softmax + geometric frame (fused) ----------------
__global__ void merged_frame_kernel(const float* __restrict__ mlog,
                                    const float* __restrict__ ad, const float* __restrict__ S,
                                    const float* __restrict__ v3d, float* __restrict__ frame) {
    int row = blockIdx.x;          // b*N + i
    int b = row >> 10;
    int tid = threadIdx.x;         // 256
    __shared__ float probs[Nc];
    __shared__ float v3s[Nc*3];
    __shared__ float sh[256];
    for (int tn = tid; tn < 768; tn += 256)
        *(float4*)&v3s[tn*4] = *(const float4*)&v3d[b*Nc*3 + tn*4];
    float4 lv = *(const float4*)&mlog[(size_t)row*Nc + tid*4];
    float e0 = __expf(lv.x), e1 = __expf(lv.y), e2 = __expf(lv.z), e3 = __expf(lv.w);
    sh[tid] = e0 + e1 + e2 + e3; __syncthreads();
    for (int st = 128; st > 0; st >>= 1) {
        if (tid < st) sh[tid] += sh[tid+st];
        __syncthreads();
    }
    float inv = 1.f / sh[0];
    float4 pr = {e0*inv, e1*inv, e2*inv, e3*inv};
    *(float4*)&probs[tid*4] = pr;
    __syncthreads();
    float cx = 0.f, cy = 0.f, cz = 0.f;
    {
        int j0 = tid * 4;
        size_t base = ((size_t)row*Nc + j0)*3;
        float4 A0 = *(const float4*)&ad[base];
        float4 A1 = *(const float4*)&ad[base+4];
        float4 A2 = *(const float4*)&ad[base+8];
        float4 S0 = *(const float4*)&S[base];
        float4 S1 = *(const float4*)&S[base+4];
        float4 S2 = *(const float4*)&S[base+8];
        float af[12] = {A0.x,A0.y,A0.z,A0.w,A1.x,A1.y,A1.z,A1.w,A2.x,A2.y,A2.z,A2.w};
        float sf[12] = {S0.x,S0.y,S0.z,S0.w,S1.x,S1.y,S1.z,S1.w,S2.x,S2.y,S2.z,S2.w};
#pragma unroll
        for (int jj = 0; jj < 4; jj++) {
            int j = j0 + jj;
            float m = probs[j];
            float ax = af[jj*3+0], ay = af[jj*3+1], az = af[jj*3+2];
            float bx = sf[jj*3+0]*v3s[j*3+0];
            float by = sf[jj*3+1]*v3s[j*3+1];
            float bz = sf[jj*3+2]*v3s[j*3+2];
            cx += m * (ay*bz - az*by);
            cy += m * (az*bx - ax*bz);
            cz += m * (ax*by - ay*bx);
        }
    }
    float vals[3] = {cx, cy, cz};
#pragma unroll
    for (int c = 0; c < 3; c++) {
        sh[tid] = vals[c]; __syncthreads();
        for (int st = 128; st > 0; st >>= 1) {
            if (tid < st) sh[tid] += sh[tid+st];
            __syncthreads();
        }
        if (tid == 0) frame[row*3 + c] = sh[0] * (1.f/Nc);
        __syncthreads();
    }
}

// ---------------- host driver ----------------
extern "C" void kernel_launch(void* const* d_in, const int* in_sizes, int n_in,
                              void* d_out, int out_size) {
    const float* x_rigid = (const float*)d_in[0];
    const float* ad      = (const float*)d_in[1];
    const float* orient  = (const float*)d_in[2];
    const float* dist    = (const float*)d_in[3];
    const int*   amask   = (const int*)  d_in[4];
    const float* Wq   = (const float*)d_in[5];
    const float* bq   = (const float*)d_in[6];
    const float* Wk   = (const float*)d_in[7];
    const float* bk   = (const float*)d_in[8];
    const float* Wv   = (const float*)d_in[9];
    const float* bv   = (const float*)d_in[10];
    const float* W3   = (const float*)d_in[11];
    const float* b3   = (const float*)d_in[12];
    const float* Wmlp = (const float*)d_in[13];
    const float* bmlp = (const float*)d_in[14];
    const float* Wfc  = (const float*)d_in[15];
    const float* bfc  = (const float*)d_in[16];
    const float* Wff1 = (const float*)d_in[17];
    const float* bff1 = (const float*)d_in[18];
    const float* Wff2 = (const float*)d_in[19];
    const float* bff2 = (const float*)d_in[20];
    const float* ln1g = (const float*)d_in[21];
    const float* ln1b = (const float*)d_in[22];
    const float* ln2g = (const float*)d_in[23];
    const float* ln2b = (const float*)d_in[24];

    float *px, *ph, *pq, *pk, *pv, *pav, *pml, *pS, *pbias, *pv3, *pfr, *pff;
    cudaGetSymbolAddress((void**)&px,  g_x);
    cudaGetSymbolAddress((void**)&ph,  g_h);
    cudaGetSymbolAddress((void**)&pq,  g_q);
    cudaGetSymbolAddress((void**)&pk,  g_k);
    cudaGetSymbolAddress((void**)&pv,  g_v);
    cudaGetSymbolAddress((void**)&pav, g_attnv);
    cudaGetSymbolAddress((void**)&pml, g_mlogits);
    cudaGetSymbolAddress((void**)&pS,  g_S);
    cudaGetSymbolAddress((void**)&pbias, g_bias);
    cudaGetSymbolAddress((void**)&pv3, g_v3d);
    cudaGetSymbolAddress((void**)&pfr, g_frame);
    cudaGetSymbolAddress((void**)&pff, g_ff);

    cudaFuncSetAttribute(attn_kernel, cudaFuncAttributeMaxDynamicSharedMemorySize, ATTN_SMEM);

    precomp_S<<<(BNN+255)/256, 256>>>(orient, pS);
    table_kernel<<<(Lc*(TBL+1)+255)/256, 256>>>(Wmlp, bmlp);
    bias_kernel<<<(BNN+255)/256, 256>>>(dist, amask, pbias);

    dim3 gQKV3(Dc/64, Mrows/64, 3);   // (6,32,3)
    dim3 gFC(Dc/64, Mrows/64);        // (6,32)
    dim3 gFF1(DFFc/64, Mrows/64);     // (8,32)

    for (int l = 0; l < Lc; l++) {
        const float* xin = (l == 0) ? x_rigid : px;
        float* ff2out = (l == Lc-1) ? (float*)d_out : px;
        ln_kernel<<<Mrows, 128>>>(xin, ln1g + l*Dc, ln1b + l*Dc, ph);
        gemm3_mma_kernel<<<gQKV3, 128>>>(ph, Wq + l*Dc*Dc, Wk + l*Dc*Dc, Wv + l*Dc*Dc,
                                         bq + l*Dc, bk + l*Dc, bv + l*Dc, pq, pk, pv);
        v3_kernel<<<Mrows/8, 256>>>(ph, W3 + l*Dc*3, b3 + l*3, pv3);
        attn_kernel<<<768, 128, ATTN_SMEM>>>(pq, pk, pv, pbias + (size_t)l*BNN, pav, pml);
        merged_frame_kernel<<<Mrows, 256>>>(pml, ad, pS, pv3, pfr);
        // FC: K=384 clean; frame contribution via rank-3 epilogue tail (Wfc rows 384..386)
        gemm_mma_kernel<<<gFC, 128>>>(pav, Dc, Wfc + (size_t)l*(Dc+3)*Dc, bfc + l*Dc,
                                      px, xin, Dc, 0, pfr, Wfc + (size_t)l*(Dc+3)*Dc + (size_t)Dc*Dc);
        ln_kernel<<<Mrows, 128>>>(px, ln2g + l*Dc, ln2b + l*Dc, ph);
        gemm_mma_kernel<<<gFF1, 128>>>(ph, Dc, Wff1 + (size_t)l*Dc*DFFc, bff1 + l*DFFc,
                                       pff, nullptr, DFFc, 1, nullptr, nullptr);
        gemm_mma_kernel<<<gFC, 128>>>(pff, DFFc, Wff2 + (size_t)l*DFFc*Dc, bff2 + l*Dc,
                                      ff2out, px, Dc, 0, nullptr, nullptr);
    }
}